// round 6
// baseline (speedup 1.0000x reference)
#include <cuda_runtime.h>
#include <cuda_bf16.h>

#define SLOTS 4                 // batches per 256-thread block
#define NT 32
#define MC 4
#define NITER_MAX 64
#define LOG2E 1.4426950408889634f

union f2u { float2 f; unsigned long long u; };

static __device__ __forceinline__ float2 fma2(float2 a, float2 b, float2 c) {
    f2u A, Bv, C, D; A.f = a; Bv.f = b; C.f = c;
    asm("fma.rn.f32x2 %0, %1, %2, %3;" : "=l"(D.u) : "l"(A.u), "l"(Bv.u), "l"(C.u));
    return D.f;
}
static __device__ __forceinline__ float2 mul2(float2 a, float2 b) {
    f2u A, Bv, D; A.f = a; Bv.f = b;
    asm("mul.rn.f32x2 %0, %1, %2;" : "=l"(D.u) : "l"(A.u), "l"(Bv.u));
    return D.f;
}
static __device__ __forceinline__ float rcp_fast(float x) {
    float r; asm("rcp.approx.f32 %0, %1;" : "=f"(r) : "f"(x)); return r;
}

// 64 threads per batch element (2 warps). Thread (row, j): row = half-warp
// lane pair index, j = lane&1. Holds HH[row][16j:16j+16] as 8 float2 regs and
// constellation channels {2j, 2j+1}. Cross-half scalars via shfl_xor(.,1).
__global__ void __launch_bounds__(SLOTS * 64, 4)
cmdnet_kernel(const float* __restrict__ yt,
              const float* __restrict__ Ht,
              const float* __restrict__ sigmat0,
              const float* __restrict__ m_c,
              const float* __restrict__ alpha,
              const float* __restrict__ taui,
              const float* __restrict__ delta,
              float* __restrict__ out,
              int B, int NR, int NITER)
{
    __shared__ __align__(16) float2 s_lasc[NITER_MAX][2];  // la[2j..]*sc*log2e
    __shared__ __align__(16) float4 s_p[NITER_MAX];        // {-sc_raw, -ta, d*log2e, 0}
    __shared__ __align__(16) float2 s_lafin[2];            // la[2j..]*tauN*log2e
    __shared__ float s_tauN;
    __shared__ __align__(16) float s_stage[SLOTS][8][NT];
    __shared__ float s_y[SLOTS][64];
    __shared__ __align__(16) float s_xt[2][SLOTS][NT];

    const int tid  = threadIdx.x;
    const int slot = tid >> 6;          // batch slot in block
    const int g    = tid & 63;          // thread within batch
    const int row  = g >> 1;            // HH row 0..31  (pairs are adjacent lanes)
    const int j    = g & 1;             // column/channel half

    if (tid < NITER) {
        float ta = fabsf(taui[tid]);
        float scale_raw = (tid == 0) ? 1.0f : ta;    // first_iter softmax scale = 1
        float sc = scale_raw * LOG2E;
        s_lasc[tid][0] = make_float2(logf(alpha[0]) * sc, logf(alpha[1]) * sc);
        s_lasc[tid][1] = make_float2(logf(alpha[2]) * sc, logf(alpha[3]) * sc);
        s_p[tid] = make_float4(-scale_raw, -ta, delta[tid] * LOG2E, 0.0f);
    }
    if (tid == 0) {
        float tn = fabsf(taui[NITER]);
        s_tauN = tn;
        float tl2 = tn * LOG2E;
        s_lafin[0] = make_float2(logf(alpha[0]) * tl2, logf(alpha[1]) * tl2);
        s_lafin[1] = make_float2(logf(alpha[2]) * tl2, logf(alpha[3]) * tl2);
    }

    const int b  = blockIdx.x * SLOTS + slot;
    const int bb = (b < B) ? b : (B - 1);          // clamp; stores guarded

    const float* Hb = Ht + (size_t)bb * NR * NT;

    // y into shared (one float per thread)
    s_y[slot][g] = yt[(size_t)bb * NR + g];
    __syncthreads();

    // ---------------- Phase 1: half HH row per thread + yH ----------------
    float2 hh2[8];
    #pragma unroll
    for (int c = 0; c < 8; c++) hh2[c] = make_float2(0.0f, 0.0f);
    float yH = 0.0f;

    const int lr = g >> 3;              // row-in-group this thread loads
    const int lc = (g & 7) * 4;         // col this thread loads (float4)

    for (int r0 = 0; r0 < NR; r0 += 8) {
        float4 hv = *reinterpret_cast<const float4*>(&Hb[(r0 + lr) * NT + lc]);
        *reinterpret_cast<float4*>(&s_stage[slot][lr][lc]) = hv;
        __syncthreads();
        #pragma unroll
        for (int rr = 0; rr < 8; rr++) {
            float h = s_stage[slot][rr][row];              // 2-lane broadcast
            yH = fmaf(s_y[slot][r0 + rr], h, yH);
            const float2 h2 = make_float2(h, h);
            #pragma unroll
            for (int kk = 0; kk < 4; kk++) {
                float4 v = *reinterpret_cast<const float4*>(&s_stage[slot][rr][16 * j + 4 * kk]);
                hh2[2 * kk + 0] = fma2(h2, make_float2(v.x, v.y), hh2[2 * kk + 0]);
                hh2[2 * kk + 1] = fma2(h2, make_float2(v.z, v.w), hh2[2 * kk + 1]);
            }
        }
        __syncthreads();
    }

    // ---------------- Phase 2: 64 iterations ----------------
    const float2 m2 = make_float2(m_c[2 * j], m_c[2 * j + 1]);   // my 2 channels
    float2 Gn2 = make_float2(0.0f, 0.0f);                         // -G*log2e
    float2 sig2_2, nsig2_2;
    { float s = sigmat0[bb]; float s2 = s * s;
      sig2_2 = make_float2(s2, s2); nsig2_2 = make_float2(-s2, -s2); }

    float2 e2 = make_float2(0.f, 0.f);
    float inv = 0.0f, xt = 0.0f;

    for (int it = 0; it < NITER; it++) {
        const float2 lasc = s_lasc[it][j];
        const float4 p    = s_p[it];            // {-sc_raw, -ta, d*log2e}
        const int buf = it & 1;

        // z (log2 domain) for my 2 channels
        float2 z = fma2(make_float2(p.x, p.x), Gn2, lasc);
        float mxp = fmaxf(z.x, z.y);
        float mx  = fmaxf(mxp, __shfl_xor_sync(0xFFFFFFFFu, mxp, 1));
        e2.x = exp2f(z.x - mx);
        e2.y = exp2f(z.y - mx);
        float sp  = e2.x + e2.y;
        float emp = fmaf(e2.y, m2.y, e2.x * m2.x);
        float sum = sp  + __shfl_xor_sync(0xFFFFFFFFu, sp, 1);
        float em  = emp + __shfl_xor_sync(0xFFFFFFFFu, emp, 1);
        inv = rcp_fast(sum);
        xt  = em * inv;

        if (j == 0) s_xt[buf][slot][row] = xt;
        __syncthreads();

        // acc_row = sum_k xt_k * HH[row][k]; my 16 columns then pair-combine
        float2 acc2 = make_float2(0.f, 0.f);
        #pragma unroll
        for (int kk = 0; kk < 4; kk++) {
            float4 v = *reinterpret_cast<const float4*>(&s_xt[buf][slot][16 * j + 4 * kk]);
            acc2 = fma2(make_float2(v.x, v.y), hh2[2 * kk + 0], acc2);
            acc2 = fma2(make_float2(v.z, v.w), hh2[2 * kk + 1], acc2);
        }
        float accp = acc2.x + acc2.y;
        float acc  = accp + __shfl_xor_sync(0xFFFFFFFFu, accp, 1);

        // grad + state update for my 2 channels
        const float c  = (yH - acc) * p.y;      // = ta*(acc - yH)
        const float ci = c * inv;
        float2 eg = make_float2(exp2f(Gn2.x), exp2f(Gn2.y));     // exp(-G)
        float2 t  = fma2(nsig2_2, eg, sig2_2);                   // sig2*(1-eg)
        float2 d  = make_float2(m2.x - xt, m2.y - xt);
        float2 w  = mul2(e2, d);
        float2 gl = fma2(make_float2(ci, ci), w, t);
        Gn2 = fma2(make_float2(p.z, p.z), gl, Gn2);              // Gn += d*l2e*gl
    }

    // ---------------- Final layer ----------------
    float2 f2v;
    {
        const float tn = s_tauN;
        float2 z = fma2(make_float2(-tn, -tn), Gn2, s_lafin[j]);
        float mxp = fmaxf(z.x, z.y);
        float mx  = fmaxf(mxp, __shfl_xor_sync(0xFFFFFFFFu, mxp, 1));
        e2.x = exp2f(z.x - mx);
        e2.y = exp2f(z.y - mx);
        float sp  = e2.x + e2.y;
        float sum = sp + __shfl_xor_sync(0xFFFFFFFFu, sp, 1);
        float iv  = __fdividef(1.0f, sum);
        f2v = make_float2(e2.x * iv, e2.y * iv);
        float emp = fmaf(f2v.y, m2.y, f2v.x * m2.x);
        xt = emp + __shfl_xor_sync(0xFFFFFFFFu, emp, 1);
    }

    // ---------------- Write out: ft [B,NT,MC] then xt [B,NT] ----------------
    if (b < B) {
        // thread g writes 8 contiguous bytes at offset g*8 of this batch's ft
        float2* dst = reinterpret_cast<float2*>(out + ((size_t)b * NT) * MC);
        dst[g] = f2v;                                   // fully coalesced
        if (j == 0) out[(size_t)B * NT * MC + (size_t)b * NT + row] = xt;
    }
}

extern "C" void kernel_launch(void* const* d_in, const int* in_sizes, int n_in,
                              void* d_out, int out_size)
{
    const float* yt     = (const float*)d_in[0];
    const float* Ht     = (const float*)d_in[1];
    const float* sig    = (const float*)d_in[2];
    const float* m      = (const float*)d_in[3];
    const float* alpha  = (const float*)d_in[4];
    const float* taui   = (const float*)d_in[5];
    const float* delta  = (const float*)d_in[6];

    const int B     = in_sizes[2];
    const int NR    = in_sizes[0] / B;
    const int NITER = in_sizes[6];

    const int blocks = (B + SLOTS - 1) / SLOTS;
    cmdnet_kernel<<<blocks, SLOTS * 64>>>(
        yt, Ht, sig, m, alpha, taui, delta, (float*)d_out, B, NR, NITER);
}

// round 7
// speedup vs baseline: 1.2662x; 1.2662x over previous
#include <cuda_runtime.h>
#include <cuda_bf16.h>

#define WARPS_PER_BLOCK 8
#define NT 32
#define MC 4
#define NITER_MAX 64
#define LOG2E 1.4426950408889634f

union f2u { float2 f; unsigned long long u; };

static __device__ __forceinline__ float2 fma2(float2 a, float2 b, float2 c) {
    f2u A, Bv, C, D; A.f = a; Bv.f = b; C.f = c;
    asm("fma.rn.f32x2 %0, %1, %2, %3;" : "=l"(D.u) : "l"(A.u), "l"(Bv.u), "l"(C.u));
    return D.f;
}
static __device__ __forceinline__ float2 mul2(float2 a, float2 b) {
    f2u A, Bv, D; A.f = a; Bv.f = b;
    asm("mul.rn.f32x2 %0, %1, %2;" : "=l"(D.u) : "l"(A.u), "l"(Bv.u));
    return D.f;
}
static __device__ __forceinline__ float2 add2(float2 a, float2 b) {
    f2u A, Bv, D; A.f = a; Bv.f = b;
    asm("add.rn.f32x2 %0, %1, %2;" : "=l"(D.u) : "l"(A.u), "l"(Bv.u));
    return D.f;
}
static __device__ __forceinline__ float rcp_fast(float x) {
    float r; asm("rcp.approx.f32 %0, %1;" : "=f"(r) : "f"(x)); return r;
}

// One warp per batch element. Lane i owns row i of HH as 16 float2 regs and
// the state Gn = -G*log2e as 2 float2. Packed fma.rn.f32x2 for the heavy FMA
// blocks. __launch_bounds__(256,3) caps regs at ~85 -> 24 warps/SM.
__global__ void __launch_bounds__(WARPS_PER_BLOCK * 32, 3)
cmdnet_kernel(const float* __restrict__ yt,
              const float* __restrict__ Ht,
              const float* __restrict__ sigmat0,
              const float* __restrict__ m_c,
              const float* __restrict__ alpha,
              const float* __restrict__ taui,
              const float* __restrict__ delta,
              float* __restrict__ out,
              int B, int NR, int NITER)
{
    __shared__ __align__(16) float4 s_lasc[NITER_MAX];  // la_j * scale_it * log2e
    __shared__ __align__(16) float4 s_p1[NITER_MAX];    // {-sc, -sc, -ta, d*log2e}
    __shared__ float s_la[MC];                           // log(alpha_j)
    __shared__ float s_tauN, s_tauNl2;                   // |taui[N]|, |taui[N]|*log2e
    __shared__ __align__(16) float s_stage[WARPS_PER_BLOCK][4][NT];
    __shared__ __align__(16) float s_xt[2][WARPS_PER_BLOCK][NT];

    const int tid   = threadIdx.x;
    const int wslot = tid >> 5;
    const int lane  = tid & 31;

    if (tid < NITER) {
        float ta = fabsf(taui[tid]);
        float scale_raw = (tid == 0) ? 1.0f : ta;     // first_iter softmax scale = 1
        float sc = scale_raw * LOG2E;
        float4 l;
        l.x = logf(alpha[0]) * sc;
        l.y = logf(alpha[1]) * sc;
        l.z = logf(alpha[2]) * sc;
        l.w = logf(alpha[3]) * sc;
        s_lasc[tid] = l;
        float4 p;
        p.x = -scale_raw;
        p.y = -scale_raw;
        p.z = -ta;
        p.w = delta[tid] * LOG2E;
        s_p1[tid] = p;
    }
    if (tid < MC) s_la[tid] = logf(alpha[tid]);
    if (tid == 0) {
        float tn = fabsf(taui[NITER]);
        s_tauN   = tn;
        s_tauNl2 = tn * LOG2E;
    }
    __syncthreads();

    const int b = blockIdx.x * WARPS_PER_BLOCK + wslot;
    if (b >= B) return;

    const float* Hb = Ht + (size_t)b * NR * NT;
    const float* yb = yt + (size_t)b * NR;

    // ---------------- Phase 1: HH row (per lane, packed f32x2) + yH ----------
    // 4-row groups: small live set so ptxas fits the 85-reg cap without
    // touching the phase-2 hot loop.
    float2 hh2[NT / 2];
    #pragma unroll
    for (int k = 0; k < NT / 2; k++) hh2[k] = make_float2(0.0f, 0.0f);
    float yH = 0.0f;

    for (int r0 = 0; r0 < NR; r0 += 4) {
        float h[4];
        #pragma unroll
        for (int rr = 0; rr < 4; rr++) {
            h[rr] = Hb[(r0 + rr) * NT + lane];           // coalesced 128B/row
            s_stage[wslot][rr][lane] = h[rr];
            yH = fmaf(yb[r0 + rr], h[rr], yH);           // broadcast LDG
        }
        __syncwarp();
        #pragma unroll
        for (int rr = 0; rr < 4; rr++) {
            const float2 h2 = make_float2(h[rr], h[rr]);
            #pragma unroll
            for (int kk = 0; kk < 8; kk++) {
                float4 v = *reinterpret_cast<const float4*>(&s_stage[wslot][rr][4 * kk]);
                hh2[2 * kk + 0] = fma2(h2, make_float2(v.x, v.y), hh2[2 * kk + 0]);
                hh2[2 * kk + 1] = fma2(h2, make_float2(v.z, v.w), hh2[2 * kk + 1]);
            }
        }
        __syncwarp();
    }

    // ---------------- Phase 2: 64 iterations ----------------
    float2 m2[2];
    m2[0] = make_float2(m_c[0], m_c[1]);
    m2[1] = make_float2(m_c[2], m_c[3]);

    float2 Gn2[2] = {make_float2(0.f, 0.f), make_float2(0.f, 0.f)}; // -G*log2e
    float sig2;
    { float s = sigmat0[b]; sig2 = s * s; }
    const float2 sig2_2  = make_float2(sig2, sig2);
    const float2 nsig2_2 = make_float2(-sig2, -sig2);

    float e0, e1, e2, e3;
    float inv = 0.0f, xt = 0.0f;

    for (int it = 0; it < NITER; it++) {
        const float4 lasc = s_lasc[it];
        const float4 p    = s_p1[it];     // {-sc, -sc, -ta, d*log2e}
        const float2 sc2  = make_float2(p.x, p.y);
        const int buf = it & 1;

        // z (log2 domain) = lasc - Gn*scale  (packed)
        float2 z0 = fma2(sc2, Gn2[0], make_float2(lasc.x, lasc.y));
        float2 z1 = fma2(sc2, Gn2[1], make_float2(lasc.z, lasc.w));
        float mx = fmaxf(fmaxf(z0.x, z0.y), fmaxf(z1.x, z1.y));
        e0 = exp2f(z0.x - mx); e1 = exp2f(z0.y - mx);
        e2 = exp2f(z1.x - mx); e3 = exp2f(z1.y - mx);
        float sum = (e0 + e1) + (e2 + e3);
        inv = rcp_fast(sum);

        // soft symbol: xt = (sum_j e_j m_j) * inv
        float em = e0 * m2[0].x;
        em = fmaf(e1, m2[0].y, em);
        em = fmaf(e2, m2[1].x, em);
        em = fmaf(e3, m2[1].y, em);
        xt = em * inv;

        // broadcast xt across the warp (double-buffered), packed xHH dot
        s_xt[buf][wslot][lane] = xt;
        __syncwarp();
        float2 acc0 = make_float2(0.f, 0.f), acc1 = make_float2(0.f, 0.f);
        #pragma unroll
        for (int kk = 0; kk < 8; kk++) {
            float4 v = *reinterpret_cast<const float4*>(&s_xt[buf][wslot][4 * kk]);
            acc0 = fma2(make_float2(v.x, v.y), hh2[2 * kk + 0], acc0);
            acc1 = fma2(make_float2(v.z, v.w), hh2[2 * kk + 1], acc1);
        }
        float acc = (acc0.x + acc0.y) + (acc1.x + acc1.y);

        // grad_L_j = sig2*(1-exp(-G_j)) + ci * e_j*(m_j - xt),  ci = ta*(xHH-yH)*inv
        const float c  = (yH - acc) * p.z;       // = ta*(acc - yH)
        const float ci = c * inv;
        const float2 ci2  = make_float2(ci, ci);
        const float2 dl2  = make_float2(p.w, p.w);
        const float2 nxt2 = make_float2(-xt, -xt);
        const float2 eg0 = make_float2(exp2f(Gn2[0].x), exp2f(Gn2[0].y)); // exp(-G)
        const float2 eg1 = make_float2(exp2f(Gn2[1].x), exp2f(Gn2[1].y));
        float2 t0 = fma2(nsig2_2, eg0, sig2_2);  // sig2*(1-eg)
        float2 t1 = fma2(nsig2_2, eg1, sig2_2);
        float2 d0 = add2(m2[0], nxt2);           // m - xt
        float2 d1 = add2(m2[1], nxt2);
        float2 w0 = mul2(make_float2(e0, e1), d0);
        float2 w1 = mul2(make_float2(e2, e3), d1);
        float2 g0 = fma2(ci2, w0, t0);
        float2 g1 = fma2(ci2, w1, t1);
        Gn2[0] = fma2(dl2, g0, Gn2[0]);          // Gn += d*log2e*gl
        Gn2[1] = fma2(dl2, g1, Gn2[1]);
    }

    // ---------------- Final layer: softmax + soft symbol ----------------
    float f[MC];
    {
        const float tl2 = s_tauNl2, tn = s_tauN;
        const float2 ntn2 = make_float2(-tn, -tn);
        float2 z0 = fma2(ntn2, Gn2[0], make_float2(s_la[0] * tl2, s_la[1] * tl2));
        float2 z1 = fma2(ntn2, Gn2[1], make_float2(s_la[2] * tl2, s_la[3] * tl2));
        float mx = fmaxf(fmaxf(z0.x, z0.y), fmaxf(z1.x, z1.y));
        e0 = exp2f(z0.x - mx); e1 = exp2f(z0.y - mx);
        e2 = exp2f(z1.x - mx); e3 = exp2f(z1.y - mx);
        float sum = (e0 + e1) + (e2 + e3);
        float iv = __fdividef(1.0f, sum);
        f[0] = e0 * iv; f[1] = e1 * iv; f[2] = e2 * iv; f[3] = e3 * iv;
        float em = f[0] * m2[0].x;
        em = fmaf(f[1], m2[0].y, em);
        em = fmaf(f[2], m2[1].x, em);
        em = fmaf(f[3], m2[1].y, em);
        xt = em;
    }

    // ---------------- Write out: ft [B,NT,MC] then xt [B,NT] ----------------
    const size_t base = (size_t)b * NT + lane;
    float4 o;
    o.x = f[0]; o.y = f[1]; o.z = f[2]; o.w = f[3];
    *reinterpret_cast<float4*>(&out[base * MC]) = o;     // coalesced 16B stores
    out[(size_t)B * NT * MC + base] = xt;
}

extern "C" void kernel_launch(void* const* d_in, const int* in_sizes, int n_in,
                              void* d_out, int out_size)
{
    const float* yt     = (const float*)d_in[0];
    const float* Ht     = (const float*)d_in[1];
    const float* sig    = (const float*)d_in[2];
    const float* m      = (const float*)d_in[3];
    const float* alpha  = (const float*)d_in[4];
    const float* taui   = (const float*)d_in[5];
    const float* delta  = (const float*)d_in[6];

    const int B     = in_sizes[2];
    const int NR    = in_sizes[0] / B;
    const int NITER = in_sizes[6];

    const int blocks = (B + WARPS_PER_BLOCK - 1) / WARPS_PER_BLOCK;
    cmdnet_kernel<<<blocks, WARPS_PER_BLOCK * 32>>>(
        yt, Ht, sig, m, alpha, taui, delta, (float*)d_out, B, NR, NITER);
}

// round 8
// speedup vs baseline: 1.3271x; 1.0481x over previous
#include <cuda_runtime.h>
#include <cuda_bf16.h>

#define WARPS_PER_BLOCK 8
#define NT 32
#define MC 4
#define NITER_MAX 64
#define LOG2E 1.4426950408889634f

union f2u { float2 f; unsigned long long u; };

static __device__ __forceinline__ float2 fma2(float2 a, float2 b, float2 c) {
    f2u A, Bv, C, D; A.f = a; Bv.f = b; C.f = c;
    asm("fma.rn.f32x2 %0, %1, %2, %3;" : "=l"(D.u) : "l"(A.u), "l"(Bv.u), "l"(C.u));
    return D.f;
}
static __device__ __forceinline__ float2 mul2(float2 a, float2 b) {
    f2u A, Bv, D; A.f = a; Bv.f = b;
    asm("mul.rn.f32x2 %0, %1, %2;" : "=l"(D.u) : "l"(A.u), "l"(Bv.u));
    return D.f;
}
static __device__ __forceinline__ float2 add2(float2 a, float2 b) {
    f2u A, Bv, D; A.f = a; Bv.f = b;
    asm("add.rn.f32x2 %0, %1, %2;" : "=l"(D.u) : "l"(A.u), "l"(Bv.u));
    return D.f;
}
static __device__ __forceinline__ float rcp_fast(float x) {
    float r; asm("rcp.approx.f32 %0, %1;" : "=f"(r) : "f"(x)); return r;
}

// One warp per batch element. Lane i owns row i of HH as 16 float2 regs and
// the state Gn = -G*log2e as 2 float2. Packed fma.rn.f32x2 on the heavy FMA
// blocks; softmax runs max-free (G is barrier-bounded); exp2(Gn) hoisted to
// the top of each iteration so MUFU overlaps the softmax MUFU.
__global__ void __launch_bounds__(WARPS_PER_BLOCK * 32, 3)
cmdnet_kernel(const float* __restrict__ yt,
              const float* __restrict__ Ht,
              const float* __restrict__ sigmat0,
              const float* __restrict__ m_c,
              const float* __restrict__ alpha,
              const float* __restrict__ taui,
              const float* __restrict__ delta,
              float* __restrict__ out,
              int B, int NR, int NITER)
{
    __shared__ __align__(16) float4 s_lasc[NITER_MAX];  // la_j * scale_it * log2e
    __shared__ __align__(16) float4 s_p1[NITER_MAX];    // {-sc, -sc, -ta, d*log2e}
    __shared__ float s_la[MC];                           // log(alpha_j)
    __shared__ float s_tauN, s_tauNl2;                   // |taui[N]|, |taui[N]|*log2e
    __shared__ __align__(16) float s_stage[WARPS_PER_BLOCK][4][NT];
    __shared__ __align__(16) float s_xt[2][WARPS_PER_BLOCK][NT];

    const int tid   = threadIdx.x;
    const int wslot = tid >> 5;
    const int lane  = tid & 31;

    if (tid < NITER) {
        float ta = fabsf(taui[tid]);
        float scale_raw = (tid == 0) ? 1.0f : ta;     // first_iter softmax scale = 1
        float sc = scale_raw * LOG2E;
        float4 l;
        l.x = logf(alpha[0]) * sc;
        l.y = logf(alpha[1]) * sc;
        l.z = logf(alpha[2]) * sc;
        l.w = logf(alpha[3]) * sc;
        s_lasc[tid] = l;
        float4 p;
        p.x = -scale_raw;
        p.y = -scale_raw;
        p.z = -ta;
        p.w = delta[tid] * LOG2E;
        s_p1[tid] = p;
    }
    if (tid < MC) s_la[tid] = logf(alpha[tid]);
    if (tid == 0) {
        float tn = fabsf(taui[NITER]);
        s_tauN   = tn;
        s_tauNl2 = tn * LOG2E;
    }
    __syncthreads();

    const int b = blockIdx.x * WARPS_PER_BLOCK + wslot;
    if (b >= B) return;

    const float* Hb = Ht + (size_t)b * NR * NT;
    const float* yb = yt + (size_t)b * NR;

    // ---------------- Phase 1: HH row (per lane, packed f32x2) + yH ----------
    float2 hh2[NT / 2];
    #pragma unroll
    for (int k = 0; k < NT / 2; k++) hh2[k] = make_float2(0.0f, 0.0f);
    float yH = 0.0f;

    for (int r0 = 0; r0 < NR; r0 += 4) {
        float h[4];
        #pragma unroll
        for (int rr = 0; rr < 4; rr++) {
            h[rr] = Hb[(r0 + rr) * NT + lane];           // coalesced 128B/row
            s_stage[wslot][rr][lane] = h[rr];
            yH = fmaf(yb[r0 + rr], h[rr], yH);           // broadcast LDG
        }
        __syncwarp();
        #pragma unroll
        for (int rr = 0; rr < 4; rr++) {
            const float2 h2 = make_float2(h[rr], h[rr]);
            #pragma unroll
            for (int kk = 0; kk < 8; kk++) {
                float4 v = *reinterpret_cast<const float4*>(&s_stage[wslot][rr][4 * kk]);
                hh2[2 * kk + 0] = fma2(h2, make_float2(v.x, v.y), hh2[2 * kk + 0]);
                hh2[2 * kk + 1] = fma2(h2, make_float2(v.z, v.w), hh2[2 * kk + 1]);
            }
        }
        __syncwarp();
    }

    // ---------------- Phase 2: 64 iterations ----------------
    float2 m2[2];
    m2[0] = make_float2(m_c[0], m_c[1]);
    m2[1] = make_float2(m_c[2], m_c[3]);

    float2 Gn2[2] = {make_float2(0.f, 0.f), make_float2(0.f, 0.f)}; // -G*log2e
    float sig2;
    { float s = sigmat0[b]; sig2 = s * s; }
    const float2 sig2_2  = make_float2(sig2, sig2);
    const float2 nsig2_2 = make_float2(-sig2, -sig2);

    float e0, e1, e2, e3;
    float inv = 0.0f, xt = 0.0f;

    #pragma unroll 2
    for (int it = 0; it < NITER; it++) {
        const float4 lasc = s_lasc[it];
        const float4 p    = s_p1[it];     // {-sc, -sc, -ta, d*log2e}
        const float2 sc2  = make_float2(p.x, p.y);
        const int buf = it & 1;

        // barrier term first: depends only on loop-carried Gn -> MUFU overlaps
        const float2 eg0 = make_float2(exp2f(Gn2[0].x), exp2f(Gn2[0].y)); // exp(-G)
        const float2 eg1 = make_float2(exp2f(Gn2[1].x), exp2f(Gn2[1].y));
        float2 t0 = fma2(nsig2_2, eg0, sig2_2);  // sig2*(1-exp(-G))
        float2 t1 = fma2(nsig2_2, eg1, sig2_2);

        // z (log2 domain) = lasc - Gn*scale; max-free softmax
        float2 z0 = fma2(sc2, Gn2[0], make_float2(lasc.x, lasc.y));
        float2 z1 = fma2(sc2, Gn2[1], make_float2(lasc.z, lasc.w));
        e0 = exp2f(z0.x); e1 = exp2f(z0.y);
        e2 = exp2f(z1.x); e3 = exp2f(z1.y);
        float sum = (e0 + e1) + (e2 + e3);
        inv = rcp_fast(sum);

        // soft symbol: xt = (sum_j e_j m_j) * inv
        float em = e0 * m2[0].x;
        em = fmaf(e1, m2[0].y, em);
        em = fmaf(e2, m2[1].x, em);
        em = fmaf(e3, m2[1].y, em);
        xt = em * inv;

        // broadcast xt across the warp (double-buffered), packed xHH dot (4 accs)
        s_xt[buf][wslot][lane] = xt;
        __syncwarp();
        float2 a0 = make_float2(0.f, 0.f), a1 = make_float2(0.f, 0.f);
        float2 a2 = make_float2(0.f, 0.f), a3 = make_float2(0.f, 0.f);
        #pragma unroll
        for (int kk = 0; kk < 4; kk++) {
            float4 v0 = *reinterpret_cast<const float4*>(&s_xt[buf][wslot][8 * kk]);
            float4 v1 = *reinterpret_cast<const float4*>(&s_xt[buf][wslot][8 * kk + 4]);
            a0 = fma2(make_float2(v0.x, v0.y), hh2[4 * kk + 0], a0);
            a1 = fma2(make_float2(v0.z, v0.w), hh2[4 * kk + 1], a1);
            a2 = fma2(make_float2(v1.x, v1.y), hh2[4 * kk + 2], a2);
            a3 = fma2(make_float2(v1.z, v1.w), hh2[4 * kk + 3], a3);
        }
        float2 as = add2(add2(a0, a1), add2(a2, a3));
        float acc = as.x + as.y;

        // grad_L_j = t_j + ci * e_j*(m_j - xt),  ci = ta*(xHH-yH)*inv
        const float c  = (yH - acc) * p.z;       // = ta*(acc - yH)
        const float ci = c * inv;
        const float2 ci2  = make_float2(ci, ci);
        const float2 dl2  = make_float2(p.w, p.w);
        const float2 nxt2 = make_float2(-xt, -xt);
        float2 d0 = add2(m2[0], nxt2);           // m - xt
        float2 d1 = add2(m2[1], nxt2);
        float2 w0 = mul2(make_float2(e0, e1), d0);
        float2 w1 = mul2(make_float2(e2, e3), d1);
        float2 g0 = fma2(ci2, w0, t0);
        float2 g1 = fma2(ci2, w1, t1);
        Gn2[0] = fma2(dl2, g0, Gn2[0]);          // Gn += d*log2e*gl
        Gn2[1] = fma2(dl2, g1, Gn2[1]);
    }

    // ---------------- Final layer: max-free softmax + soft symbol ------------
    float f[MC];
    {
        const float tl2 = s_tauNl2, tn = s_tauN;
        const float2 ntn2 = make_float2(-tn, -tn);
        float2 z0 = fma2(ntn2, Gn2[0], make_float2(s_la[0] * tl2, s_la[1] * tl2));
        float2 z1 = fma2(ntn2, Gn2[1], make_float2(s_la[2] * tl2, s_la[3] * tl2));
        e0 = exp2f(z0.x); e1 = exp2f(z0.y);
        e2 = exp2f(z1.x); e3 = exp2f(z1.y);
        float sum = (e0 + e1) + (e2 + e3);
        float iv = __fdividef(1.0f, sum);
        f[0] = e0 * iv; f[1] = e1 * iv; f[2] = e2 * iv; f[3] = e3 * iv;
        float em = f[0] * m2[0].x;
        em = fmaf(f[1], m2[0].y, em);
        em = fmaf(f[2], m2[1].x, em);
        em = fmaf(f[3], m2[1].y, em);
        xt = em;
    }

    // ---------------- Write out: ft [B,NT,MC] then xt [B,NT] ----------------
    const size_t base = (size_t)b * NT + lane;
    float4 o;
    o.x = f[0]; o.y = f[1]; o.z = f[2]; o.w = f[3];
    *reinterpret_cast<float4*>(&out[base * MC]) = o;     // coalesced 16B stores
    out[(size_t)B * NT * MC + base] = xt;
}

extern "C" void kernel_launch(void* const* d_in, const int* in_sizes, int n_in,
                              void* d_out, int out_size)
{
    const float* yt     = (const float*)d_in[0];
    const float* Ht     = (const float*)d_in[1];
    const float* sig    = (const float*)d_in[2];
    const float* m      = (const float*)d_in[3];
    const float* alpha  = (const float*)d_in[4];
    const float* taui   = (const float*)d_in[5];
    const float* delta  = (const float*)d_in[6];

    const int B     = in_sizes[2];
    const int NR    = in_sizes[0] / B;
    const int NITER = in_sizes[6];

    const int blocks = (B + WARPS_PER_BLOCK - 1) / WARPS_PER_BLOCK;
    cmdnet_kernel<<<blocks, WARPS_PER_BLOCK * 32>>>(
        yt, Ht, sig, m, alpha, taui, delta, (float*)d_out, B, NR, NITER);
}